// round 1
// baseline (speedup 1.0000x reference)
#include <cuda_runtime.h>

#define CIN   128
#define HW    96
#define HWSZ  (HW*HW)      // 9216
#define BATCH 4
#define OC1   128
#define OC2   108
#define NDG   4
#define CG    32

// ---------------- scratch (static device globals; no allocs) ----------------
__device__ float g_xres[BATCH * OC1 * HWSZ];   // conv1 output (18.9 MB)
__device__ float g_co  [BATCH * OC2 * HWSZ];   // conv2 output (15.9 MB)
__device__ float g_w1t [CIN * 9 * OC1];        // conv1 weights transposed [ic][k][oc]
__device__ float g_w2t [CIN * 9 * OC2];        // conv2 weights transposed
__device__ float g_wdt [CIN * 9 * OC1];        // dcn   weights transposed

// ---------------- packed f32x2 helpers ----------------
__device__ __forceinline__ unsigned long long pack2(float lo, float hi) {
    unsigned long long r;
    asm("mov.b64 %0, {%1, %2};" : "=l"(r) : "f"(lo), "f"(hi));
    return r;
}
__device__ __forceinline__ void unpack2(unsigned long long v, float& lo, float& hi) {
    asm("mov.b64 {%0, %1}, %2;" : "=f"(lo), "=f"(hi) : "l"(v));
}
__device__ __forceinline__ unsigned long long ffma2(unsigned long long a,
                                                    unsigned long long b,
                                                    unsigned long long c) {
    unsigned long long d;
    asm("fma.rn.f32x2 %0, %1, %2, %3;" : "=l"(d) : "l"(a), "l"(b), "l"(c));
    return d;
}

// ---------------- weight transpose: dst[ic][k][oc] = src[oc][ic][k] ----------------
__global__ void transpose_w_kernel(const float* __restrict__ src, int OC, int which) {
    float* dst = (which == 0) ? g_w1t : (which == 1) ? g_w2t : g_wdt;
    int i = blockIdx.x * 256 + threadIdx.x;
    int total = OC * CIN * 9;
    if (i >= total) return;
    int oc  = i / (CIN * 9);
    int rem = i % (CIN * 9);
    int ic  = rem / 9;
    int k   = rem % 9;
    dst[(ic * 9 + k) * OC + oc] = src[i];
}

// ---------------- conv3x3, pad=1, NCHW ----------------
// Block: 256 threads = 4 oc-groups x 64 px-threads. Spatial tile 32x8,
// each px-thread owns 4 consecutive columns; each thread accumulates 8 oc
// as 4 packed f32x2 pairs -> 4px x 4pair = 16 b64 accumulators.
// MODE 0: x_vq -> g_xres (w = g_w1t). MODE 1: g_xres -> g_co (w = g_w2t).
template<int OC, int MODE>
__global__ __launch_bounds__(256) void conv3x3_kernel(const float* __restrict__ xin,
                                                      const float* __restrict__ bias) {
    const float* x  = (MODE == 0) ? xin : g_xres;
    const float* wt = (MODE == 0) ? g_w1t : g_w2t;
    float*       y  = (MODE == 0) ? g_xres : g_co;

    const int tid    = threadIdx.x;
    const int b      = blockIdx.y;
    const int ocb    = blockIdx.z;                 // 32 oc per block
    const int tile_x = (blockIdx.x % 3) * 32;
    const int tile_y = (blockIdx.x / 3) * 8;
    const int oc_grp = tid >> 6;                   // 0..3
    const int pt     = tid & 63;
    const int ty     = pt >> 3;                    // 0..7
    const int tx     = pt & 7;                     // 0..7 (x4 cols)

    __shared__ float in_s[8 * 10 * 34];                  // [ic][r(10)][c(34)]
    __shared__ __align__(8) float sw[8 * 9 * 32];        // [ic][k][oc_l]

    unsigned long long acc[4][4];
#pragma unroll
    for (int i = 0; i < 4; i++)
#pragma unroll
        for (int j = 0; j < 4; j++) acc[i][j] = 0ull;

    const float* xb = x + (size_t)b * CIN * HWSZ;

    for (int ic0 = 0; ic0 < CIN; ic0 += 8) {
        // input tile (with halo) for 8 input channels
        for (int i = tid; i < 8 * 10 * 34; i += 256) {
            int ic = i / 340, rem = i % 340;
            int r = rem / 34, c = rem % 34;
            int gy = tile_y + r - 1, gx = tile_x + c - 1;
            float v = 0.f;
            if (gy >= 0 && gy < HW && gx >= 0 && gx < HW)
                v = xb[(ic0 + ic) * HWSZ + gy * HW + gx];
            in_s[i] = v;
        }
        // weight tile: sw[ic][k][oc_l], coalesced from [ic][k][oc] layout
        for (int i = tid; i < 8 * 9 * 32; i += 256) {
            int ic = i / 288, rem = i % 288;
            int k = rem / 32, ocl = rem % 32;
            int oc = ocb * 32 + ocl;
            sw[i] = (oc < OC) ? wt[((ic0 + ic) * 9 + k) * OC + oc] : 0.f;
        }
        __syncthreads();

#pragma unroll
        for (int ic = 0; ic < 8; ic++) {
            float v[3][6];
            const float* ip = &in_s[ic * 340 + ty * 34 + tx * 4];
#pragma unroll
            for (int r = 0; r < 3; r++)
#pragma unroll
                for (int c = 0; c < 6; c++) v[r][c] = ip[r * 34 + c];
#pragma unroll
            for (int k = 0; k < 9; k++) {
                const int dr = k / 3, dc = k % 3;
                unsigned long long w2[4];
                const float* wp = &sw[ic * 288 + k * 32 + oc_grp * 8];
#pragma unroll
                for (int p = 0; p < 4; p++)
                    w2[p] = *reinterpret_cast<const unsigned long long*>(wp + 2 * p);
#pragma unroll
                for (int px = 0; px < 4; px++) {
                    unsigned long long v2 = pack2(v[dr][px + dc], v[dr][px + dc]);
#pragma unroll
                    for (int p = 0; p < 4; p++)
                        acc[px][p] = ffma2(v2, w2[p], acc[px][p]);
                }
            }
        }
        __syncthreads();
    }

    // epilogue: float4 store per oc (coalesced)
    const int gy = tile_y + ty, gx0 = tile_x + tx * 4;
#pragma unroll
    for (int p = 0; p < 4; p++) {
        int oc = ocb * 32 + oc_grp * 8 + 2 * p;
        float lo[4], hi[4];
#pragma unroll
        for (int px = 0; px < 4; px++) unpack2(acc[px][p], lo[px], hi[px]);
        if (oc < OC) {
            float bz = bias[oc];
            float4 o = make_float4(lo[0] + bz, lo[1] + bz, lo[2] + bz, lo[3] + bz);
            *reinterpret_cast<float4*>(&y[((size_t)(b * OC + oc)) * HWSZ + gy * HW + gx0]) = o;
        }
        if (oc + 1 < OC) {
            float bz = bias[oc + 1];
            float4 o = make_float4(hi[0] + bz, hi[1] + bz, hi[2] + bz, hi[3] + bz);
            *reinterpret_cast<float4*>(&y[((size_t)(b * OC + oc + 1)) * HWSZ + gy * HW + gx0]) = o;
        }
    }
}

// ---------------- modulated deformable conv ----------------
// Block: 256 threads = 16 oc-groups x 16 px-threads. Spatial tile 32x2 = 64 px.
// Per (g,k): compute bilinear params (mask+validity folded into corner weights),
// gather col[32ic][64px] into smem, smem GEMM 128oc x 64px x 32ic with f32x2.
__global__ __launch_bounds__(256) void dcn_kernel(const float* __restrict__ x,
                                                  const float* __restrict__ bias,
                                                  float* __restrict__ y) {
    const int tid    = threadIdx.x;
    const int b      = blockIdx.y;
    const int tile_x = (blockIdx.x % 3) * 32;
    const int tile_y = (blockIdx.x / 3) * 2;
    const int oc_grp = tid >> 4;                 // 0..15 -> 8 oc each
    const int px_t   = tid & 15;                 // 0..15 -> 4 px each

    __shared__ __align__(8)  float s_w[32 * 128];   // [ic][oc]
    __shared__ __align__(16) float s_col[32 * 64];  // [ic][px]
    __shared__ int   s_idx[64][4];
    __shared__ float s_wgt[64][4];

    unsigned long long acc[4][4];
#pragma unroll
    for (int i = 0; i < 4; i++)
#pragma unroll
        for (int j = 0; j < 4; j++) acc[i][j] = 0ull;

    const float* cob = g_co + (size_t)b * OC2 * HWSZ;
    const float* xb  = x    + (size_t)b * CIN * HWSZ;

    for (int g = 0; g < NDG; g++) {
        for (int k = 0; k < 9; k++) {
            // Phase A: bilinear sampling params for 64 pixels
            if (tid < 64) {
                int px  = tid;
                int gy  = tile_y + (px >> 5);
                int gx  = tile_x + (px & 31);
                int c_y = g * 18 + 2 * k;
                float offy = cob[c_y * HWSZ + gy * HW + gx];
                float offx = cob[(c_y + 1) * HWSZ + gy * HW + gx];
                float mraw = cob[(72 + g * 9 + k) * HWSZ + gy * HW + gx];
                float m  = 1.f / (1.f + expf(-mraw));
                float ys = (float)gy + (float)(k / 3 - 1) + offy;
                float xs = (float)gx + (float)(k % 3 - 1) + offx;
                float y0f = floorf(ys), x0f = floorf(xs);
                float fy = ys - y0f, fx = xs - x0f;
                int y0 = (int)y0f, x0 = (int)x0f;
#pragma unroll
                for (int cnr = 0; cnr < 4; cnr++) {
                    int dy = cnr >> 1, dx = cnr & 1;
                    int yi = y0 + dy, xi = x0 + dx;
                    bool valid = (yi >= 0) && (yi < HW) && (xi >= 0) && (xi < HW);
                    float wy = dy ? fy : (1.f - fy);
                    float wx = dx ? fx : (1.f - fx);
                    int yc = min(max(yi, 0), HW - 1);
                    int xc = min(max(xi, 0), HW - 1);
                    s_idx[px][cnr] = yc * HW + xc;
                    s_wgt[px][cnr] = valid ? (wy * wx * m) : 0.f;
                }
            }
            // Phase A2: weight tile [ic(32)][oc(128)] for this (g,k), coalesced
            {
                const float* wsrc = g_wdt + (size_t)(g * 32) * 9 * 128 + k * 128;
#pragma unroll
                for (int j = 0; j < 16; j++) {
                    int i  = tid + j * 256;
                    int ic = i >> 7, oc = i & 127;
                    s_w[i] = wsrc[ic * 9 * 128 + oc];
                }
            }
            __syncthreads();

            // Phase B: gather col tile (x is L2-resident)
#pragma unroll
            for (int j = 0; j < 8; j++) {
                int e  = tid + j * 256;
                int ic = e >> 6, px = e & 63;
                const float* xp = xb + (size_t)(g * 32 + ic) * HWSZ;
                float v = s_wgt[px][0] * xp[s_idx[px][0]]
                        + s_wgt[px][1] * xp[s_idx[px][1]]
                        + s_wgt[px][2] * xp[s_idx[px][2]]
                        + s_wgt[px][3] * xp[s_idx[px][3]];
                s_col[e] = v;
            }
            __syncthreads();

            // Phase C: 128oc x 64px x 32ic GEMM slice
#pragma unroll
            for (int ic = 0; ic < 32; ic++) {
                float4 c4 = *reinterpret_cast<const float4*>(&s_col[ic * 64 + px_t * 4]);
                unsigned long long w2[4];
                const float* wp = &s_w[ic * 128 + oc_grp * 8];
#pragma unroll
                for (int p = 0; p < 4; p++)
                    w2[p] = *reinterpret_cast<const unsigned long long*>(wp + 2 * p);
                float cv[4] = {c4.x, c4.y, c4.z, c4.w};
#pragma unroll
                for (int px = 0; px < 4; px++) {
                    unsigned long long v2 = pack2(cv[px], cv[px]);
#pragma unroll
                    for (int p = 0; p < 4; p++)
                        acc[px][p] = ffma2(v2, w2[p], acc[px][p]);
                }
            }
            __syncthreads();
        }
    }

    // epilogue
    const int gy  = tile_y + (px_t >> 3);
    const int gx0 = tile_x + (px_t & 7) * 4;
#pragma unroll
    for (int p = 0; p < 4; p++) {
        int oc = oc_grp * 8 + 2 * p;
        float lo[4], hi[4];
#pragma unroll
        for (int px = 0; px < 4; px++) unpack2(acc[px][p], lo[px], hi[px]);
        float bz0 = bias[oc];
        float4 o0 = make_float4(lo[0] + bz0, lo[1] + bz0, lo[2] + bz0, lo[3] + bz0);
        *reinterpret_cast<float4*>(&y[((size_t)(b * OC1 + oc)) * HWSZ + gy * HW + gx0]) = o0;
        float bz1 = bias[oc + 1];
        float4 o1 = make_float4(hi[0] + bz1, hi[1] + bz1, hi[2] + bz1, hi[3] + bz1);
        *reinterpret_cast<float4*>(&y[((size_t)(b * OC1 + oc + 1)) * HWSZ + gy * HW + gx0]) = o1;
    }
}

// ---------------- launch ----------------
extern "C" void kernel_launch(void* const* d_in, const int* in_sizes, int n_in,
                              void* d_out, int out_size) {
    (void)in_sizes; (void)n_in; (void)out_size;
    const float* x_vq  = (const float*)d_in[0];
    const float* w_off = (const float*)d_in[1];
    const float* b_off = (const float*)d_in[2];
    const float* w_co  = (const float*)d_in[3];
    const float* b_co  = (const float*)d_in[4];
    const float* w_dcn = (const float*)d_in[5];
    const float* b_dcn = (const float*)d_in[6];
    float* out = (float*)d_out;

    // weight transposes (cheap, every call — kernel_launch must be stateless)
    transpose_w_kernel<<<(OC1 * CIN * 9 + 255) / 256, 256>>>(w_off, OC1, 0);
    transpose_w_kernel<<<(OC2 * CIN * 9 + 255) / 256, 256>>>(w_co,  OC2, 1);
    transpose_w_kernel<<<(OC1 * CIN * 9 + 255) / 256, 256>>>(w_dcn, OC1, 2);

    dim3 cgrid(36, BATCH, 4);   // 3x12 spatial tiles, batch, oc-blocks of 32
    conv3x3_kernel<OC1, 0><<<cgrid, 256>>>(x_vq, b_off);
    conv3x3_kernel<OC2, 1><<<cgrid, 256>>>(nullptr, b_co);

    dim3 dgrid(3 * 48, BATCH);  // 32x2 px tiles
    dcn_kernel<<<dgrid, 256>>>(x_vq, b_dcn, out);
}